// round 6
// baseline (speedup 1.0000x reference)
#include <cuda_runtime.h>

// CombinedLoraA: out[c, r] = sum_k x[xids[c*64+r], k] * A[wids[c], k, r]
//   x:[512,1,4096] f32  xids:[20480] i32  wids:[320] i32  A:[80,4096,64] f32
//   out:[320,1,64] f32
//
// R5: R4 with init_kernel fixed (256-thread block must LOOP over all 320 c's;
// R4 dropped c=256..319 -> wrong perm). Two-kernel graph:
//   init_kernel: block 0 groups c's by adapter (brute-force rank, no scan);
//                blocks 1..80 zero out (out accumulates via atomics).
//   lora_main:   per CTA (k-range, adapter-slot): 32-k slice of ALL 512 x rows
//                in smem (XOR swizzle); A[w,krange,r] in 32 regs; per c-visit
//                8 LDS.128 + 32 FMA + atomicAdd into out.

constexpr int KDIM   = 4096;
constexpr int RANK   = 64;
constexpr int CDIM   = 320;
constexpr int NADAPT = 80;
constexpr int NTOK   = 512;
constexpr int KR     = 32;               // k per range
constexpr int NKR    = KDIM / KR;        // 128
constexpr int ASPLIT = 7;                // grid 128*7 = 896 CTAs
constexpr int NTHR   = 256;
constexpr int NPAIR  = CDIM * RANK;      // 20480

constexpr int SMEM_BYTES = NTOK * KR * 4 + CDIM * 4 + (NADAPT + 1) * 4;

__device__ int g_perm[CDIM];
__device__ int g_seg[NADAPT + 1];

// ---- init: zero out + group c's by adapter ----
__global__ void init_kernel(const int* __restrict__ wids, float* __restrict__ out)
{
    const int tid = threadIdx.x;
    if (blockIdx.x > 0) {
        out[(blockIdx.x - 1) * 256 + tid] = 0.0f;
        return;
    }
    __shared__ int wid_s[CDIM];
    for (int i = tid; i < CDIM; i += blockDim.x) wid_s[i] = wids[i];
    __syncthreads();
    // rank of each c among (wid, c) pairs -> perm slot  (covers ALL 320 c's)
    for (int c = tid; c < CDIM; c += blockDim.x) {
        const int w = wid_s[c];
        int pos = 0;
#pragma unroll 8
        for (int c2 = 0; c2 < CDIM; ++c2) {
            const int w2 = wid_s[c2];
            pos += (w2 < w) || (w2 == w && c2 < c);
        }
        g_perm[pos] = c;
    }
    if (tid < NADAPT + 1) {
        int s = 0;
#pragma unroll 8
        for (int c2 = 0; c2 < CDIM; ++c2) s += (wid_s[c2] < tid);
        g_seg[tid] = s;
    }
}

// ---- main: one CTA = (k-range, adapter-slot) ----
__global__ __launch_bounds__(NTHR, 3) void lora_main(
    const float* __restrict__ x,
    const int*   __restrict__ xids,
    const float* __restrict__ A,
    float*       __restrict__ out)
{
    extern __shared__ float smem[];
    float4* xs4    = reinterpret_cast<float4*>(smem);          // 512 rows x 8 f4 slots
    int*    perm_s = reinterpret_cast<int*>(smem + NTOK * KR);
    int*    seg_s  = perm_s + CDIM;

    const int tid   = threadIdx.x;
    const int kr0   = blockIdx.x * KR;
    const int aslot = blockIdx.y;

    // stage x k-range for ALL 512 rows; slot = k4 ^ (row&7)
    for (int i = tid; i < NTOK * 8; i += NTHR) {
        const int row = i >> 3, k4 = i & 7;
        const float4 v = *reinterpret_cast<const float4*>(
            x + (size_t)row * KDIM + kr0 + k4 * 4);
        xs4[row * 8 + (k4 ^ (row & 7))] = v;
    }
    for (int i = tid; i < CDIM; i += NTHR)       perm_s[i] = g_perm[i];
    for (int i = tid; i < NADAPT + 1; i += NTHR) seg_s[i]  = g_seg[i];
    __syncthreads();

    const int r = tid & 63;          // rank index (lane-contiguous)
    const int g = tid >> 6;          // 4 independent thread-groups
    const int w_lo = (aslot * NADAPT) / ASPLIT;
    const int w_hi = ((aslot + 1) * NADAPT) / ASPLIT;

    for (int w = w_lo + g; w < w_hi; w += 4) {
        const int lo = seg_s[w], hi = seg_s[w + 1];
        if (lo >= hi) continue;

        // A[w, kr0..kr0+32, r] -> 32 registers (coalesced over r)
        float a[KR];
        const float* __restrict__ Ap = A + ((size_t)w * KDIM + kr0) * RANK + r;
#pragma unroll
        for (int j = 0; j < KR; ++j) a[j] = Ap[j * RANK];

        // software-pipelined token fetch
        int ci = lo;
        int c  = perm_s[ci];
        int t  = xids[c * 64 + r];
        while (ci < hi) {
            const int c_cur = c, t_cur = t;
            ++ci;
            if (ci < hi) { c = perm_s[ci]; t = xids[c * 64 + r]; }

            const int s = t_cur & 7;
            const float4* __restrict__ xrow = xs4 + t_cur * 8;
            float acc0 = 0.f, acc1 = 0.f, acc2 = 0.f, acc3 = 0.f;
#pragma unroll
            for (int k4 = 0; k4 < 8; ++k4) {
                const float4 xv = xrow[k4 ^ s];
                acc0 = fmaf(a[k4 * 4 + 0], xv.x, acc0);
                acc1 = fmaf(a[k4 * 4 + 1], xv.y, acc1);
                acc2 = fmaf(a[k4 * 4 + 2], xv.z, acc2);
                acc3 = fmaf(a[k4 * 4 + 3], xv.w, acc3);
            }
            atomicAdd(out + c_cur * 64 + r, (acc0 + acc1) + (acc2 + acc3));
        }
    }
}

extern "C" void kernel_launch(void* const* d_in, const int* in_sizes, int n_in,
                              void* d_out, int out_size)
{
    const float* x    = (const float*)d_in[0];
    const int*   xids = (const int*)  d_in[1];
    const int*   wids = (const int*)  d_in[2];
    const float* A    = (const float*)d_in[3];
    float*       out  = (float*)d_out;

    cudaFuncSetAttribute(lora_main,
                         cudaFuncAttributeMaxDynamicSharedMemorySize, SMEM_BYTES);

    init_kernel<<<1 + NPAIR / 256, 256>>>(wids, out);
    lora_main<<<dim3(NKR, ASPLIT), NTHR, SMEM_BYTES>>>(x, xids, A, out);
}